// round 12
// baseline (speedup 1.0000x reference)
#include <cuda_runtime.h>
#include <cstdint>

#define BATCH   2048
#define INSZ    40960
#define KC      64
#define KSTPT   640
#define NTILE   64
#define TOTS    (NTILE * KSTPT)
#define ASTRW   20                  // words per 64-int8 row (16 + 4 pad)
#define A_WORDS (128 * ASTRW)
#define BUF_WORDS (2 * A_WORDS)
#define SMEM_BYTES (2 * BUF_WORDS * 4)   // 40960

#define TW2_STRIDE 516
#define TW2_FLOATS (32 * TW2_STRIDE)
#define TCOMB_STRIDE 516
#define TCOMB_FLOATS (8 * TCOMB_STRIDE)
#define TAIL_SMEM_BYTES ((TW2_FLOATS + TCOMB_FLOATS + 8 * 32) * 4)

#define MAGIC 12582912.f            // 1.5 * 2^23
#define XSCALE 255.f
#define WSCALE 25700.f

__device__ float g_partial[(size_t)NTILE * 4 * 128 * 128];

__device__ __forceinline__ float crelu(float x) { return fminf(fmaxf(x, 0.f), 1.f); }

// quantize 4 floats (v*s rounded via magic trick) and pack low bytes into one u32
__device__ __forceinline__ uint32_t q4(float4 v, float s) {
    uint32_t b0 = __float_as_uint(fmaf(v.x, s, MAGIC));
    uint32_t b1 = __float_as_uint(fmaf(v.y, s, MAGIC));
    uint32_t b2 = __float_as_uint(fmaf(v.z, s, MAGIC));
    uint32_t b3 = __float_as_uint(fmaf(v.w, s, MAGIC));
    return __byte_perm(__byte_perm(b0, b1, 0x0040), __byte_perm(b2, b3, 0x0040), 0x5410);
}

__device__ __forceinline__ void imma32(int& c0, int& c1, int& c2, int& c3,
                                       uint32_t a0, uint32_t a1, uint32_t a2, uint32_t a3,
                                       uint32_t b0, uint32_t b1) {
    asm volatile(
        "mma.sync.aligned.m16n8k32.row.col.s32.u8.s8.s32 "
        "{%0,%1,%2,%3}, {%4,%5,%6,%7}, {%8,%9}, {%0,%1,%2,%3};"
        : "+r"(c0), "+r"(c1), "+r"(c2), "+r"(c3)
        : "r"(a0), "r"(a1), "r"(a2), "r"(a3), "r"(b0), "r"(b1));
}

__device__ __forceinline__ int owner_of(int s, int G) {
    return (int)((long)s * G / TOTS);
}

// ========== Kernel 1: FT GEMM, u8*s8 IMMA m16n8k32, even stage-partition ==========
__global__ void __launch_bounds__(256, 1)
ft_kernel(const float* __restrict__ xp, const float* __restrict__ xo,
          const float* __restrict__ wp, const float* __restrict__ wo)
{
    extern __shared__ uint32_t sm[];
    const int tid = threadIdx.x, lane = tid & 31, wid = tid >> 5;
    const int G = gridDim.x, ib = blockIdx.x;
    int S = (int)((long)ib * TOTS / G);
    const int S_hi = (int)((long)(ib + 1) * TOTS / G);
    const uint32_t smb = (uint32_t)__cvta_generic_to_shared(sm);
    const int wm = (wid & 3) * 32;
    const int wn = (wid >> 2) * 64;

    while (S < S_hi) {
        const int t    = S / KSTPT;
        const int send = min(S_hi, (t + 1) * KSTPT);
        const int ks0  = S - t * KSTPT;
        const int len  = send - S;
        const int persp = t >> 5, mt = (t >> 1) & 15, nt = t & 1;
        const float* __restrict__ X = persp ? xo : xp;
        const float* __restrict__ W = persp ? wo : wp;
        const int m0 = mt * 128, n0 = nt * 128;
        const size_t kbase = (size_t)ks0 * KC;

        const float* aptr[8]; const float* bptr[8];
        uint32_t asw[8], bsw[8];
        #pragma unroll
        for (int j = 0; j < 8; j++) {
            int f = tid + j * 256, r = f >> 4, q = f & 15;
            aptr[j] = X + (size_t)(m0 + r) * INSZ + kbase + q * 4;
            bptr[j] = W + (size_t)(n0 + r) * INSZ + kbase + q * 4;
            asw[j] = smb + 4u * (r * ASTRW + q);
            bsw[j] = smb + 4u * (A_WORDS + r * ASTRW + q);
        }

        int acc[2][8][4];
        #pragma unroll
        for (int a = 0; a < 2; a++)
            #pragma unroll
            for (int b = 0; b < 8; b++)
                #pragma unroll
                for (int c = 0; c < 4; c++) acc[a][b][c] = 0;

        float4 ra[8], rb[8];
        #pragma unroll
        for (int j = 0; j < 8; j++) ra[j] = *reinterpret_cast<const float4*>(aptr[j]);
        #pragma unroll
        for (int j = 0; j < 8; j++) rb[j] = *reinterpret_cast<const float4*>(bptr[j]);
        #pragma unroll
        for (int j = 0; j < 8; j++) {
            uint32_t u = q4(ra[j], XSCALE);
            asm volatile("st.shared.b32 [%0], %1;" :: "r"(asw[j]), "r"(u) : "memory");
            uint32_t v = q4(rb[j], WSCALE);
            asm volatile("st.shared.b32 [%0], %1;" :: "r"(bsw[j]), "r"(v) : "memory");
        }
        __syncthreads();
        if (len > 1) {
            #pragma unroll
            for (int j = 0; j < 8; j++) ra[j] = *reinterpret_cast<const float4*>(aptr[j] + KC);
            #pragma unroll
            for (int j = 0; j < 8; j++) rb[j] = *reinterpret_cast<const float4*>(bptr[j] + KC);
        }

        for (int s2 = 0; s2 < len; s2++) {
            const int buf = s2 & 1;
            if (s2 + 1 < len) {
                const uint32_t boff = (uint32_t)((buf ^ 1) * BUF_WORDS * 4);
                #pragma unroll
                for (int j = 0; j < 8; j++) {
                    uint32_t u = q4(ra[j], XSCALE);
                    asm volatile("st.shared.b32 [%0], %1;" :: "r"(asw[j] + boff), "r"(u) : "memory");
                    uint32_t v = q4(rb[j], WSCALE);
                    asm volatile("st.shared.b32 [%0], %1;" :: "r"(bsw[j] + boff), "r"(v) : "memory");
                }
            }
            if (s2 + 2 < len) {
                const size_t ko = (size_t)(s2 + 2) * KC;
                #pragma unroll
                for (int j = 0; j < 8; j++) ra[j] = *reinterpret_cast<const float4*>(aptr[j] + ko);
                #pragma unroll
                for (int j = 0; j < 8; j++) rb[j] = *reinterpret_cast<const float4*>(bptr[j] + ko);
            }
            const uint32_t* sa = sm + buf * BUF_WORDS;
            const uint32_t* sb = sa + A_WORDS;
            #pragma unroll
            for (int c = 0; c < 2; c++) {            // two k32 chunks
                const int kw = (lane & 3) + 8 * c;
                uint32_t af[2][4], bf[8][2];
                #pragma unroll
                for (int mtl = 0; mtl < 2; mtl++) {
                    const int r = wm + mtl * 16 + (lane >> 2);
                    af[mtl][0] = sa[r * ASTRW + kw];
                    af[mtl][1] = sa[(r + 8) * ASTRW + kw];
                    af[mtl][2] = sa[r * ASTRW + kw + 4];
                    af[mtl][3] = sa[(r + 8) * ASTRW + kw + 4];
                }
                #pragma unroll
                for (int ntl = 0; ntl < 8; ntl++) {
                    const int rn = wn + ntl * 8 + (lane >> 2);
                    bf[ntl][0] = sb[rn * ASTRW + kw];
                    bf[ntl][1] = sb[rn * ASTRW + kw + 4];
                }
                #pragma unroll
                for (int mtl = 0; mtl < 2; mtl++)
                    #pragma unroll
                    for (int ntl = 0; ntl < 8; ntl++)
                        imma32(acc[mtl][ntl][0], acc[mtl][ntl][1],
                               acc[mtl][ntl][2], acc[mtl][ntl][3],
                               af[mtl][0], af[mtl][1], af[mtl][2], af[mtl][3],
                               bf[ntl][0], bf[ntl][1]);
            }
            __syncthreads();
        }

        const int slot = ib - owner_of(t * KSTPT, G);
        float* gp = g_partial + ((size_t)t * 4 + slot) * 16384;
        const float sc = 1.f / (XSCALE * WSCALE);
        #pragma unroll
        for (int mtl = 0; mtl < 2; mtl++) {
            const int ml = wm + mtl * 16 + (lane >> 2);
            #pragma unroll
            for (int ntl = 0; ntl < 8; ntl++) {
                const int col = wn + ntl * 8 + (lane & 3) * 2;
                *reinterpret_cast<float2*>(&gp[(size_t)ml * 128 + col]) =
                    make_float2((float)acc[mtl][ntl][0] * sc, (float)acc[mtl][ntl][1] * sc);
                *reinterpret_cast<float2*>(&gp[(size_t)(ml + 8) * 128 + col]) =
                    make_float2((float)acc[mtl][ntl][2] * sc, (float)acc[mtl][ntl][3] * sc);
            }
        }
        S = send;
    }
}

// ========== Kernel 2: fused nslots-reduce + bias + crelu + tail MLP ==========
__global__ void __launch_bounds__(256)
reduce_tail(const float* __restrict__ b1p, const float* __restrict__ b1o,
            const float* __restrict__ W2, const float* __restrict__ b2,
            const float* __restrict__ W3, const float* __restrict__ b3,
            const float* __restrict__ Wo, const float* __restrict__ bo,
            float* __restrict__ out, int G)
{
    extern __shared__ float ts[];
    float* W2s  = ts;
    float* comb = ts + TW2_FLOATS;
    float* h1s  = comb + TCOMB_FLOATS;
    const int tid = threadIdx.x, lane = tid & 31, wid = tid >> 5;
    const int R0 = blockIdx.x * 8;

    #pragma unroll
    for (int it = 0; it < 4; it++) {
        const int idx = it * 256 + tid;
        const int row = idx >> 7, fq = idx & 127;
        const int m = R0 + row;
        const int f = fq * 4;
        const int persp = f >> 8, ntl = (f >> 7) & 1, c = f & 127;
        const int t = persp * 32 + (m >> 7) * 2 + ntl;
        const int o0 = (int)((long)t * KSTPT * G / TOTS);
        const int o1 = (int)(((long)t * KSTPT + KSTPT - 1) * G / TOTS);
        const int ns = o1 - o0 + 1;
        const float* gp = g_partial + (size_t)t * 4 * 16384 + (size_t)(m & 127) * 128 + c;
        float4 bv = (f < 256) ? *reinterpret_cast<const float4*>(&b1p[f])
                              : *reinterpret_cast<const float4*>(&b1o[f - 256]);
        float4 s = bv;
        for (int sl = 0; sl < ns; sl++) {
            float4 v = *reinterpret_cast<const float4*>(gp + (size_t)sl * 16384);
            s.x += v.x; s.y += v.y; s.z += v.z; s.w += v.w;
        }
        float* cc = comb + row * TCOMB_STRIDE + f;
        cc[0] = crelu(s.x); cc[1] = crelu(s.y); cc[2] = crelu(s.z); cc[3] = crelu(s.w);
    }
    #pragma unroll
    for (int it = 0; it < 16; it++) {
        const int idx = it * 256 + tid;
        const int j = idx >> 7, k = (idx & 127) * 4;
        *reinterpret_cast<float4*>(&W2s[j * TW2_STRIDE + k]) =
            *reinterpret_cast<const float4*>(&W2[j * 512 + k]);
    }
    __syncthreads();

    {
        const int row = wid;
        const float* w2r = W2s + lane * TW2_STRIDE;
        const float* cr  = comb + row * TCOMB_STRIDE;
        float a = b2[lane];
        #pragma unroll 8
        for (int k4 = 0; k4 < 128; k4++) {
            float4 w = *reinterpret_cast<const float4*>(&w2r[k4 * 4]);
            float4 c = *reinterpret_cast<const float4*>(&cr[k4 * 4]);
            a += w.x * c.x + w.y * c.y + w.z * c.z + w.w * c.w;
        }
        h1s[row * 32 + lane] = crelu(a);
        __syncwarp();
        float h2 = b3[lane];
        #pragma unroll
        for (int k = 0; k < 32; k++) h2 += W3[lane * 32 + k] * h1s[row * 32 + k];
        h2 = crelu(h2);
        float v = h2 * Wo[lane];
        #pragma unroll
        for (int o = 16; o; o >>= 1) v += __shfl_xor_sync(0xFFFFFFFFu, v, o);
        if (lane == 0) out[R0 + row] = crelu(v + bo[0]);
    }
}

extern "C" void kernel_launch(void* const* d_in, const int* in_sizes, int n_in,
                              void* d_out, int out_size)
{
    const float* xp  = (const float*)d_in[0];
    const float* xo  = (const float*)d_in[1];
    const float* W1p = (const float*)d_in[2];
    const float* b1p = (const float*)d_in[3];
    const float* W1o = (const float*)d_in[4];
    const float* b1o = (const float*)d_in[5];
    const float* W2  = (const float*)d_in[6];
    const float* b2  = (const float*)d_in[7];
    const float* W3  = (const float*)d_in[8];
    const float* b3  = (const float*)d_in[9];
    const float* Wo  = (const float*)d_in[10];
    const float* bo  = (const float*)d_in[11];

    static int grid_ft = 0;
    if (grid_ft == 0) {
        int smc = 148;
        cudaDeviceGetAttribute(&smc, cudaDevAttrMultiProcessorCount, 0);
        if (smc > 160) smc = 160;
        if (smc < 64)  smc = 64;
        grid_ft = smc;
        cudaFuncSetAttribute(ft_kernel, cudaFuncAttributeMaxDynamicSharedMemorySize,
                             SMEM_BYTES);
        cudaFuncSetAttribute(reduce_tail, cudaFuncAttributeMaxDynamicSharedMemorySize,
                             TAIL_SMEM_BYTES);
    }
    ft_kernel<<<grid_ft, 256, SMEM_BYTES>>>(xp, xo, W1p, W1o);
    reduce_tail<<<256, 256, TAIL_SMEM_BYTES>>>(b1p, b1o, W2, b2, W3, b3, Wo, bo,
                                               (float*)d_out, grid_ft);
}

// round 13
// speedup vs baseline: 2.1955x; 2.1955x over previous
#include <cuda_runtime.h>
#include <cuda_fp16.h>
#include <cstdint>

#define BATCH   2048
#define INSZ    40960
#define KC      64
#define KSTPT   640
#define NTILE   64
#define TOTS    (NTILE * KSTPT)
#define ASTRW   36
#define A_WORDS (128 * ASTRW)
#define BUF_WORDS (2 * A_WORDS)
#define SMEM_BYTES (2 * BUF_WORDS * 4)   // 73728

#define TW2_STRIDE 516
#define TW2_FLOATS (32 * TW2_STRIDE)
#define TCOMB_STRIDE 516
#define TCOMB_FLOATS (8 * TCOMB_STRIDE)
#define TAIL_SMEM_BYTES ((TW2_FLOATS + TCOMB_FLOATS + 8 * 32) * 4)

__device__ float g_partial[(size_t)NTILE * 4 * 128 * 128];
__device__ float g_comb[(size_t)BATCH * 512];
__device__ int   g_counter[NTILE];        // zero-init; self-resetting each run

__device__ __forceinline__ float crelu(float x) { return fminf(fmaxf(x, 0.f), 1.f); }
__device__ __forceinline__ uint32_t f2h2(float a, float b) {
    __half2 h = __floats2half2_rn(a, b);
    return *reinterpret_cast<uint32_t*>(&h);
}
__device__ __forceinline__ void mma16(float& c0, float& c1, float& c2, float& c3,
                                      uint32_t a0, uint32_t a1, uint32_t a2, uint32_t a3,
                                      uint32_t b0, uint32_t b1) {
    asm volatile(
        "mma.sync.aligned.m16n8k16.row.col.f32.f16.f16.f32 "
        "{%0,%1,%2,%3}, {%4,%5,%6,%7}, {%8,%9}, {%0,%1,%2,%3};"
        : "+f"(c0), "+f"(c1), "+f"(c2), "+f"(c3)
        : "r"(a0), "r"(a1), "r"(a2), "r"(a3), "r"(b0), "r"(b1));
}
__device__ __forceinline__ int owner_of(int s, int G) {
    return (int)((long)s * G / TOTS);
}

// ========== Kernel 1: FT GEMM (fp16 MMA) + fused per-tile reduce/bias/crelu ========
__global__ void __launch_bounds__(256, 1)
ft_kernel(const float* __restrict__ xp, const float* __restrict__ xo,
          const float* __restrict__ wp, const float* __restrict__ wo,
          const float* __restrict__ b1p, const float* __restrict__ b1o)
{
    extern __shared__ uint32_t sm[];
    __shared__ int s_last;
    const int tid = threadIdx.x, lane = tid & 31, wid = tid >> 5;
    const int G = gridDim.x, ib = blockIdx.x;
    int S = (int)((long)ib * TOTS / G);
    const int S_hi = (int)((long)(ib + 1) * TOTS / G);
    const uint32_t smb = (uint32_t)__cvta_generic_to_shared(sm);
    const int wm = (wid & 3) * 32;
    const int wn = (wid >> 2) * 64;

    while (S < S_hi) {
        const int t    = S / KSTPT;
        const int send = min(S_hi, (t + 1) * KSTPT);
        const int ks0  = S - t * KSTPT;
        const int len  = send - S;
        const int persp = t >> 5, mt = (t >> 1) & 15, nt = t & 1;
        const float* __restrict__ X = persp ? xo : xp;
        const float* __restrict__ W = persp ? wo : wp;
        const int m0 = mt * 128, n0 = nt * 128;
        const size_t kbase = (size_t)ks0 * KC;

        const float* aptr[8]; const float* bptr[8];
        uint32_t asw[8], bsw[8];
        #pragma unroll
        for (int j = 0; j < 8; j++) {
            int f = tid + j * 256, r = f >> 4, q = f & 15;
            aptr[j] = X + (size_t)(m0 + r) * INSZ + kbase + q * 4;
            bptr[j] = W + (size_t)(n0 + r) * INSZ + kbase + q * 4;
            asw[j] = smb + 4u * (r * ASTRW + q * 2);
            bsw[j] = smb + 4u * (A_WORDS + r * ASTRW + q * 2);
        }

        float acc[2][8][4];
        #pragma unroll
        for (int a = 0; a < 2; a++)
            #pragma unroll
            for (int b = 0; b < 8; b++)
                #pragma unroll
                for (int c = 0; c < 4; c++) acc[a][b][c] = 0.f;

        float4 ra[8], rb[8];
        #pragma unroll
        for (int j = 0; j < 8; j++) ra[j] = *reinterpret_cast<const float4*>(aptr[j]);
        #pragma unroll
        for (int j = 0; j < 8; j++) rb[j] = *reinterpret_cast<const float4*>(bptr[j]);
        #pragma unroll
        for (int j = 0; j < 8; j++) {
            uint32_t u0 = f2h2(ra[j].x, ra[j].y), u1 = f2h2(ra[j].z, ra[j].w);
            asm volatile("st.shared.v2.b32 [%0], {%1,%2};" :: "r"(asw[j]), "r"(u0), "r"(u1) : "memory");
            uint32_t v0 = f2h2(rb[j].x, rb[j].y), v1 = f2h2(rb[j].z, rb[j].w);
            asm volatile("st.shared.v2.b32 [%0], {%1,%2};" :: "r"(bsw[j]), "r"(v0), "r"(v1) : "memory");
        }
        __syncthreads();
        if (len > 1) {
            #pragma unroll
            for (int j = 0; j < 8; j++) ra[j] = *reinterpret_cast<const float4*>(aptr[j] + KC);
            #pragma unroll
            for (int j = 0; j < 8; j++) rb[j] = *reinterpret_cast<const float4*>(bptr[j] + KC);
        }

        for (int s2 = 0; s2 < len; s2++) {
            const int buf = s2 & 1;
            if (s2 + 1 < len) {
                const uint32_t boff = (uint32_t)((buf ^ 1) * BUF_WORDS * 4);
                #pragma unroll
                for (int j = 0; j < 8; j++) {
                    uint32_t u0 = f2h2(ra[j].x, ra[j].y), u1 = f2h2(ra[j].z, ra[j].w);
                    asm volatile("st.shared.v2.b32 [%0], {%1,%2};" :: "r"(asw[j] + boff), "r"(u0), "r"(u1) : "memory");
                    uint32_t v0 = f2h2(rb[j].x, rb[j].y), v1 = f2h2(rb[j].z, rb[j].w);
                    asm volatile("st.shared.v2.b32 [%0], {%1,%2};" :: "r"(bsw[j] + boff), "r"(v0), "r"(v1) : "memory");
                }
            }
            if (s2 + 2 < len) {
                const size_t ko = (size_t)(s2 + 2) * KC;
                #pragma unroll
                for (int j = 0; j < 8; j++) ra[j] = *reinterpret_cast<const float4*>(aptr[j] + ko);
                #pragma unroll
                for (int j = 0; j < 8; j++) rb[j] = *reinterpret_cast<const float4*>(bptr[j] + ko);
            }
            const uint32_t* sa = sm + buf * BUF_WORDS;
            const uint32_t* sb = sa + A_WORDS;
            #pragma unroll
            for (int kk = 0; kk < 4; kk++) {
                const int kw = kk * 8 + (lane & 3);
                uint32_t af[2][4], bf[8][2];
                #pragma unroll
                for (int mtl = 0; mtl < 2; mtl++) {
                    const int r = wm + mtl * 16 + (lane >> 2);
                    af[mtl][0] = sa[r * ASTRW + kw];
                    af[mtl][1] = sa[(r + 8) * ASTRW + kw];
                    af[mtl][2] = sa[r * ASTRW + kw + 4];
                    af[mtl][3] = sa[(r + 8) * ASTRW + kw + 4];
                }
                #pragma unroll
                for (int ntl = 0; ntl < 8; ntl++) {
                    const int rn = wn + ntl * 8 + (lane >> 2);
                    bf[ntl][0] = sb[rn * ASTRW + kw];
                    bf[ntl][1] = sb[rn * ASTRW + kw + 4];
                }
                #pragma unroll
                for (int mtl = 0; mtl < 2; mtl++)
                    #pragma unroll
                    for (int ntl = 0; ntl < 8; ntl++)
                        mma16(acc[mtl][ntl][0], acc[mtl][ntl][1],
                              acc[mtl][ntl][2], acc[mtl][ntl][3],
                              af[mtl][0], af[mtl][1], af[mtl][2], af[mtl][3],
                              bf[ntl][0], bf[ntl][1]);
            }
            __syncthreads();
        }

        // ---- write this CTA's partial slot ----
        const int o0 = owner_of(t * KSTPT, G);
        const int slot = ib - o0;                     // 0..3
        const int ns = owner_of(t * KSTPT + KSTPT - 1, G) - o0 + 1;
        float* gp = g_partial + ((size_t)t * 4 + slot) * 16384;
        #pragma unroll
        for (int mtl = 0; mtl < 2; mtl++) {
            const int ml = wm + mtl * 16 + (lane >> 2);
            #pragma unroll
            for (int ntl = 0; ntl < 8; ntl++) {
                const int col = wn + ntl * 8 + (lane & 3) * 2;
                *reinterpret_cast<float2*>(&gp[(size_t)ml * 128 + col]) =
                    make_float2(acc[mtl][ntl][0], acc[mtl][ntl][1]);
                *reinterpret_cast<float2*>(&gp[(size_t)(ml + 8) * 128 + col]) =
                    make_float2(acc[mtl][ntl][2], acc[mtl][ntl][3]);
            }
        }
        // ---- last contributor reduces + bias + crelu -> g_comb ----
        __threadfence();
        __syncthreads();
        if (tid == 0) {
            int v = atomicAdd(&g_counter[t], 1);
            s_last = (v == ns - 1);
            if (s_last) g_counter[t] = 0;             // self-reset for graph replay
        }
        __syncthreads();
        if (s_last) {
            __threadfence();                          // acquire other CTAs' partials
            const float* bias = persp ? b1o : b1p;
            const float* base = g_partial + (size_t)t * 4 * 16384;
            #pragma unroll
            for (int it = 0; it < 16; it++) {
                const int idx = it * 256 + tid;       // 4096 f4 = 128 rows x 32 f4
                const int row = idx >> 5, q = (idx & 31) * 4;
                const float* gq = base + (size_t)row * 128 + q;
                float4 s4 = *reinterpret_cast<const float4*>(&bias[n0 + q]);
                for (int sl = 0; sl < ns; sl++) {
                    float4 v4 = *reinterpret_cast<const float4*>(gq + (size_t)sl * 16384);
                    s4.x += v4.x; s4.y += v4.y; s4.z += v4.z; s4.w += v4.w;
                }
                s4.x = crelu(s4.x); s4.y = crelu(s4.y);
                s4.z = crelu(s4.z); s4.w = crelu(s4.w);
                *reinterpret_cast<float4*>(
                    &g_comb[(size_t)(m0 + row) * 512 + persp * 256 + n0 + q]) = s4;
            }
        }
        S = send;
    }
}

// ========== Kernel 2: tail MLP only (reads g_comb) ==========
__global__ void __launch_bounds__(256)
tail_kernel(const float* __restrict__ W2, const float* __restrict__ b2,
            const float* __restrict__ W3, const float* __restrict__ b3,
            const float* __restrict__ Wo, const float* __restrict__ bo,
            float* __restrict__ out)
{
    extern __shared__ float ts[];
    float* W2s  = ts;                       // [32][516]
    float* comb = ts + TW2_FLOATS;          // [8][516]
    float* h1s  = comb + TCOMB_FLOATS;      // [8][32]
    const int tid = threadIdx.x, lane = tid & 31, wid = tid >> 5;
    const int R0 = blockIdx.x * 8;

    #pragma unroll
    for (int it = 0; it < 4; it++) {
        const int idx = it * 256 + tid;     // 8 rows x 128 f4
        const int row = idx >> 7, fq = (idx & 127) * 4;
        *reinterpret_cast<float4*>(&comb[row * TCOMB_STRIDE + fq]) =
            *reinterpret_cast<const float4*>(&g_comb[(size_t)(R0 + row) * 512 + fq]);
    }
    #pragma unroll
    for (int it = 0; it < 16; it++) {
        const int idx = it * 256 + tid;
        const int j = idx >> 7, k = (idx & 127) * 4;
        *reinterpret_cast<float4*>(&W2s[j * TW2_STRIDE + k]) =
            *reinterpret_cast<const float4*>(&W2[j * 512 + k]);
    }
    __syncthreads();

    {
        const int row = wid;
        const float* w2r = W2s + lane * TW2_STRIDE;
        const float* cr  = comb + row * TCOMB_STRIDE;
        float a = b2[lane];
        #pragma unroll 8
        for (int k4 = 0; k4 < 128; k4++) {
            float4 w = *reinterpret_cast<const float4*>(&w2r[k4 * 4]);
            float4 c = *reinterpret_cast<const float4*>(&cr[k4 * 4]);
            a += w.x * c.x + w.y * c.y + w.z * c.z + w.w * c.w;
        }
        h1s[row * 32 + lane] = crelu(a);
        __syncwarp();
        float h2 = b3[lane];
        #pragma unroll
        for (int k = 0; k < 32; k++) h2 += W3[lane * 32 + k] * h1s[row * 32 + k];
        h2 = crelu(h2);
        float v = h2 * Wo[lane];
        #pragma unroll
        for (int o = 16; o; o >>= 1) v += __shfl_xor_sync(0xFFFFFFFFu, v, o);
        if (lane == 0) out[R0 + row] = crelu(v + bo[0]);
    }
}

extern "C" void kernel_launch(void* const* d_in, const int* in_sizes, int n_in,
                              void* d_out, int out_size)
{
    const float* xp  = (const float*)d_in[0];
    const float* xo  = (const float*)d_in[1];
    const float* W1p = (const float*)d_in[2];
    const float* b1p = (const float*)d_in[3];
    const float* W1o = (const float*)d_in[4];
    const float* b1o = (const float*)d_in[5];
    const float* W2  = (const float*)d_in[6];
    const float* b2  = (const float*)d_in[7];
    const float* W3  = (const float*)d_in[8];
    const float* b3  = (const float*)d_in[9];
    const float* Wo  = (const float*)d_in[10];
    const float* bo  = (const float*)d_in[11];

    static int grid_ft = 0;
    if (grid_ft == 0) {
        int smc = 148;
        cudaDeviceGetAttribute(&smc, cudaDevAttrMultiProcessorCount, 0);
        if (smc > 160) smc = 160;
        if (smc < 64)  smc = 64;
        grid_ft = smc;
        cudaFuncSetAttribute(ft_kernel, cudaFuncAttributeMaxDynamicSharedMemorySize,
                             SMEM_BYTES);
        cudaFuncSetAttribute(tail_kernel, cudaFuncAttributeMaxDynamicSharedMemorySize,
                             TAIL_SMEM_BYTES);
    }
    ft_kernel<<<grid_ft, 256, SMEM_BYTES>>>(xp, xo, W1p, W1o, b1p, b1o);
    tail_kernel<<<256, 256, TAIL_SMEM_BYTES>>>(W2, b2, W3, b3, Wo, bo, (float*)d_out);
}

// round 14
// speedup vs baseline: 2.2620x; 1.0303x over previous
#include <cuda_runtime.h>
#include <cuda_fp16.h>
#include <cstdint>

#define BATCH   2048
#define INSZ    40960
#define KC      64
#define KSTPT   640
#define NTILE   64
#define TOTS    (NTILE * KSTPT)
#define ASTRW   36
#define A_WORDS (128 * ASTRW)
#define BUF_WORDS (2 * A_WORDS)
#define SMEM_BYTES (2 * BUF_WORDS * 4)   // 73728

#define TW2_STRIDE 516
#define TW2_FLOATS (32 * TW2_STRIDE)
#define TCOMB_STRIDE 516
#define TCOMB_FLOATS (8 * TCOMB_STRIDE)
#define TAIL_SMEM_BYTES ((TW2_FLOATS + TCOMB_FLOATS + 8 * 32) * 4)

__device__ float g_partial[(size_t)NTILE * 4 * 128 * 128];

__device__ __forceinline__ float crelu(float x) { return fminf(fmaxf(x, 0.f), 1.f); }
__device__ __forceinline__ uint32_t f2h2(float a, float b) {
    __half2 h = __floats2half2_rn(a, b);
    return *reinterpret_cast<uint32_t*>(&h);
}
__device__ __forceinline__ void mma16(float& c0, float& c1, float& c2, float& c3,
                                      uint32_t a0, uint32_t a1, uint32_t a2, uint32_t a3,
                                      uint32_t b0, uint32_t b1) {
    asm volatile(
        "mma.sync.aligned.m16n8k16.row.col.f32.f16.f16.f32 "
        "{%0,%1,%2,%3}, {%4,%5,%6,%7}, {%8,%9}, {%0,%1,%2,%3};"
        : "+f"(c0), "+f"(c1), "+f"(c2), "+f"(c3)
        : "r"(a0), "r"(a1), "r"(a2), "r"(a3), "r"(b0), "r"(b1));
}
__device__ __forceinline__ int owner_of(int s, int G) {
    return (int)((long)s * G / TOTS);
}

// ========== Kernel 1: FT GEMM, fp32-accum fp16 MMA, even stage-partition ==========
__global__ void __launch_bounds__(256, 1)
ft_kernel(const float* __restrict__ xp, const float* __restrict__ xo,
          const float* __restrict__ wp, const float* __restrict__ wo)
{
    extern __shared__ uint32_t sm[];
    const int tid = threadIdx.x, lane = tid & 31, wid = tid >> 5;
    const int G = gridDim.x, ib = blockIdx.x;
    int S = (int)((long)ib * TOTS / G);
    const int S_hi = (int)((long)(ib + 1) * TOTS / G);
    const uint32_t smb = (uint32_t)__cvta_generic_to_shared(sm);
    const int wm = (wid & 3) * 32;
    const int wn = (wid >> 2) * 64;

    while (S < S_hi) {
        const int t    = S / KSTPT;
        const int send = min(S_hi, (t + 1) * KSTPT);
        const int ks0  = S - t * KSTPT;
        const int len  = send - S;
        const int persp = t >> 5, mt = (t >> 1) & 15, nt = t & 1;
        const float* __restrict__ X = persp ? xo : xp;
        const float* __restrict__ W = persp ? wo : wp;
        const int m0 = mt * 128, n0 = nt * 128;
        const size_t kbase = (size_t)ks0 * KC;

        const float* aptr[8]; const float* bptr[8];
        uint32_t asw[8], bsw[8];
        #pragma unroll
        for (int j = 0; j < 8; j++) {
            int f = tid + j * 256, r = f >> 4, q = f & 15;
            aptr[j] = X + (size_t)(m0 + r) * INSZ + kbase + q * 4;
            bptr[j] = W + (size_t)(n0 + r) * INSZ + kbase + q * 4;
            asw[j] = smb + 4u * (r * ASTRW + q * 2);
            bsw[j] = smb + 4u * (A_WORDS + r * ASTRW + q * 2);
        }

        float acc[2][8][4];
        #pragma unroll
        for (int a = 0; a < 2; a++)
            #pragma unroll
            for (int b = 0; b < 8; b++)
                #pragma unroll
                for (int c = 0; c < 4; c++) acc[a][b][c] = 0.f;

        float4 ra[8], rb[8];
        #pragma unroll
        for (int j = 0; j < 8; j++) ra[j] = *reinterpret_cast<const float4*>(aptr[j]);
        #pragma unroll
        for (int j = 0; j < 8; j++) rb[j] = *reinterpret_cast<const float4*>(bptr[j]);
        #pragma unroll
        for (int j = 0; j < 8; j++) {
            uint32_t u0 = f2h2(ra[j].x, ra[j].y), u1 = f2h2(ra[j].z, ra[j].w);
            asm volatile("st.shared.v2.b32 [%0], {%1,%2};" :: "r"(asw[j]), "r"(u0), "r"(u1) : "memory");
            uint32_t v0 = f2h2(rb[j].x, rb[j].y), v1 = f2h2(rb[j].z, rb[j].w);
            asm volatile("st.shared.v2.b32 [%0], {%1,%2};" :: "r"(bsw[j]), "r"(v0), "r"(v1) : "memory");
        }
        __syncthreads();
        if (len > 1) {
            #pragma unroll
            for (int j = 0; j < 8; j++) ra[j] = *reinterpret_cast<const float4*>(aptr[j] + KC);
            #pragma unroll
            for (int j = 0; j < 8; j++) rb[j] = *reinterpret_cast<const float4*>(bptr[j] + KC);
        }

        for (int s2 = 0; s2 < len; s2++) {
            const int buf = s2 & 1;
            if (s2 + 1 < len) {
                const uint32_t boff = (uint32_t)((buf ^ 1) * BUF_WORDS * 4);
                #pragma unroll
                for (int j = 0; j < 8; j++) {
                    uint32_t u0 = f2h2(ra[j].x, ra[j].y), u1 = f2h2(ra[j].z, ra[j].w);
                    asm volatile("st.shared.v2.b32 [%0], {%1,%2};" :: "r"(asw[j] + boff), "r"(u0), "r"(u1) : "memory");
                    uint32_t v0 = f2h2(rb[j].x, rb[j].y), v1 = f2h2(rb[j].z, rb[j].w);
                    asm volatile("st.shared.v2.b32 [%0], {%1,%2};" :: "r"(bsw[j] + boff), "r"(v0), "r"(v1) : "memory");
                }
            }
            if (s2 + 2 < len) {
                const size_t ko = (size_t)(s2 + 2) * KC;
                #pragma unroll
                for (int j = 0; j < 8; j++) ra[j] = *reinterpret_cast<const float4*>(aptr[j] + ko);
                #pragma unroll
                for (int j = 0; j < 8; j++) rb[j] = *reinterpret_cast<const float4*>(bptr[j] + ko);
            }
            const uint32_t* sa = sm + buf * BUF_WORDS;
            const uint32_t* sb = sa + A_WORDS;
            #pragma unroll
            for (int kk = 0; kk < 4; kk++) {
                const int kw = kk * 8 + (lane & 3);
                uint32_t af[2][4], bf[8][2];
                #pragma unroll
                for (int mtl = 0; mtl < 2; mtl++) {
                    const int r = wm + mtl * 16 + (lane >> 2);
                    af[mtl][0] = sa[r * ASTRW + kw];
                    af[mtl][1] = sa[(r + 8) * ASTRW + kw];
                    af[mtl][2] = sa[r * ASTRW + kw + 4];
                    af[mtl][3] = sa[(r + 8) * ASTRW + kw + 4];
                }
                #pragma unroll
                for (int ntl = 0; ntl < 8; ntl++) {
                    const int rn = wn + ntl * 8 + (lane >> 2);
                    bf[ntl][0] = sb[rn * ASTRW + kw];
                    bf[ntl][1] = sb[rn * ASTRW + kw + 4];
                }
                #pragma unroll
                for (int mtl = 0; mtl < 2; mtl++)
                    #pragma unroll
                    for (int ntl = 0; ntl < 8; ntl++)
                        mma16(acc[mtl][ntl][0], acc[mtl][ntl][1],
                              acc[mtl][ntl][2], acc[mtl][ntl][3],
                              af[mtl][0], af[mtl][1], af[mtl][2], af[mtl][3],
                              bf[ntl][0], bf[ntl][1]);
            }
            __syncthreads();
        }

        const int slot = ib - owner_of(t * KSTPT, G);
        float* gp = g_partial + ((size_t)t * 4 + slot) * 16384;
        #pragma unroll
        for (int mtl = 0; mtl < 2; mtl++) {
            const int ml = wm + mtl * 16 + (lane >> 2);
            #pragma unroll
            for (int ntl = 0; ntl < 8; ntl++) {
                const int col = wn + ntl * 8 + (lane & 3) * 2;
                *reinterpret_cast<float2*>(&gp[(size_t)ml * 128 + col]) =
                    make_float2(acc[mtl][ntl][0], acc[mtl][ntl][1]);
                *reinterpret_cast<float2*>(&gp[(size_t)(ml + 8) * 128 + col]) =
                    make_float2(acc[mtl][ntl][2], acc[mtl][ntl][3]);
            }
        }
        S = send;
    }
}

// ========== Kernel 2: fused reduce + bias + crelu + tail MLP (multi-accumulator) ====
__global__ void __launch_bounds__(256)
reduce_tail(const float* __restrict__ b1p, const float* __restrict__ b1o,
            const float* __restrict__ W2, const float* __restrict__ b2,
            const float* __restrict__ W3, const float* __restrict__ b3,
            const float* __restrict__ Wo, const float* __restrict__ bo,
            float* __restrict__ out, int G)
{
    extern __shared__ float ts[];
    float* W2s  = ts;
    float* comb = ts + TW2_FLOATS;
    float* h1s  = comb + TCOMB_FLOATS;
    const int tid = threadIdx.x, lane = tid & 31, wid = tid >> 5;
    const int R0 = blockIdx.x * 8;

    #pragma unroll
    for (int it = 0; it < 4; it++) {
        const int idx = it * 256 + tid;
        const int row = idx >> 7, fq = idx & 127;
        const int m = R0 + row;
        const int f = fq * 4;
        const int persp = f >> 8, ntl = (f >> 7) & 1, c = f & 127;
        const int t = persp * 32 + (m >> 7) * 2 + ntl;
        const int o0 = (int)((long)t * KSTPT * G / TOTS);
        const int o1 = (int)(((long)t * KSTPT + KSTPT - 1) * G / TOTS);
        const int ns = o1 - o0 + 1;
        const float* gp = g_partial + (size_t)t * 4 * 16384 + (size_t)(m & 127) * 128 + c;
        float4 bv = (f < 256) ? *reinterpret_cast<const float4*>(&b1p[f])
                              : *reinterpret_cast<const float4*>(&b1o[f - 256]);
        float4 s = bv;
        for (int sl = 0; sl < ns; sl++) {
            float4 v = *reinterpret_cast<const float4*>(gp + (size_t)sl * 16384);
            s.x += v.x; s.y += v.y; s.z += v.z; s.w += v.w;
        }
        float* cc = comb + row * TCOMB_STRIDE + f;
        cc[0] = crelu(s.x); cc[1] = crelu(s.y); cc[2] = crelu(s.z); cc[3] = crelu(s.w);
    }
    #pragma unroll
    for (int it = 0; it < 16; it++) {
        const int idx = it * 256 + tid;
        const int j = idx >> 7, k = (idx & 127) * 4;
        *reinterpret_cast<float4*>(&W2s[j * TW2_STRIDE + k]) =
            *reinterpret_cast<const float4*>(&W2[j * 512 + k]);
    }
    __syncthreads();

    {
        const int row = wid;
        const float* w2r = W2s + lane * TW2_STRIDE;
        const float* cr  = comb + row * TCOMB_STRIDE;
        // 4 independent accumulator chains (breaks the 512-deep FMA dependency)
        float a0 = b2[lane], a1 = 0.f, a2 = 0.f, a3 = 0.f;
        #pragma unroll 4
        for (int k4 = 0; k4 < 128; k4 += 4) {
            float4 w0 = *reinterpret_cast<const float4*>(&w2r[k4 * 4]);
            float4 c0 = *reinterpret_cast<const float4*>(&cr[k4 * 4]);
            float4 w1 = *reinterpret_cast<const float4*>(&w2r[k4 * 4 + 4]);
            float4 c1 = *reinterpret_cast<const float4*>(&cr[k4 * 4 + 4]);
            float4 w2v = *reinterpret_cast<const float4*>(&w2r[k4 * 4 + 8]);
            float4 c2 = *reinterpret_cast<const float4*>(&cr[k4 * 4 + 8]);
            float4 w3v = *reinterpret_cast<const float4*>(&w2r[k4 * 4 + 12]);
            float4 c3 = *reinterpret_cast<const float4*>(&cr[k4 * 4 + 12]);
            a0 += w0.x * c0.x + w0.y * c0.y + w0.z * c0.z + w0.w * c0.w;
            a1 += w1.x * c1.x + w1.y * c1.y + w1.z * c1.z + w1.w * c1.w;
            a2 += w2v.x * c2.x + w2v.y * c2.y + w2v.z * c2.z + w2v.w * c2.w;
            a3 += w3v.x * c3.x + w3v.y * c3.y + w3v.z * c3.z + w3v.w * c3.w;
        }
        h1s[row * 32 + lane] = crelu((a0 + a1) + (a2 + a3));
        __syncwarp();
        float h2a = b3[lane], h2b = 0.f;
        #pragma unroll
        for (int k = 0; k < 32; k += 2) {
            h2a += W3[lane * 32 + k] * h1s[row * 32 + k];
            h2b += W3[lane * 32 + k + 1] * h1s[row * 32 + k + 1];
        }
        float h2 = crelu(h2a + h2b);
        float v = h2 * Wo[lane];
        #pragma unroll
        for (int o = 16; o; o >>= 1) v += __shfl_xor_sync(0xFFFFFFFFu, v, o);
        if (lane == 0) out[R0 + row] = crelu(v + bo[0]);
    }
}

extern "C" void kernel_launch(void* const* d_in, const int* in_sizes, int n_in,
                              void* d_out, int out_size)
{
    const float* xp  = (const float*)d_in[0];
    const float* xo  = (const float*)d_in[1];
    const float* W1p = (const float*)d_in[2];
    const float* b1p = (const float*)d_in[3];
    const float* W1o = (const float*)d_in[4];
    const float* b1o = (const float*)d_in[5];
    const float* W2  = (const float*)d_in[6];
    const float* b2  = (const float*)d_in[7];
    const float* W3  = (const float*)d_in[8];
    const float* b3  = (const float*)d_in[9];
    const float* Wo  = (const float*)d_in[10];
    const float* bo  = (const float*)d_in[11];

    static int grid_ft = 0;
    if (grid_ft == 0) {
        int smc = 148;
        cudaDeviceGetAttribute(&smc, cudaDevAttrMultiProcessorCount, 0);
        if (smc > 160) smc = 160;
        if (smc < 64)  smc = 64;
        grid_ft = smc;
        cudaFuncSetAttribute(ft_kernel, cudaFuncAttributeMaxDynamicSharedMemorySize,
                             SMEM_BYTES);
        cudaFuncSetAttribute(reduce_tail, cudaFuncAttributeMaxDynamicSharedMemorySize,
                             TAIL_SMEM_BYTES);
    }
    ft_kernel<<<grid_ft, 256, SMEM_BYTES>>>(xp, xo, W1p, W1o);
    reduce_tail<<<256, 256, TAIL_SMEM_BYTES>>>(b1p, b1o, W2, b2, W3, b3, Wo, bo,
                                               (float*)d_out, grid_ft);
}

// round 15
// speedup vs baseline: 2.2751x; 1.0058x over previous
#include <cuda_runtime.h>
#include <cuda_fp16.h>
#include <cstdint>

#define BATCH   2048
#define INSZ    40960
#define KC      64
#define KSTPT   640
#define NTILE   64
#define TOTS    (NTILE * KSTPT)
#define ASTRW   36
#define A_WORDS (128 * ASTRW)
#define BUF_WORDS (2 * A_WORDS)
#define SMEM_BYTES (2 * BUF_WORDS * 4)   // 73728

// tail smem (halfs / floats)
#define W2H_STRIDE   552                 // halfs; 276 words ≡ 20 mod 32 -> conflict-free
#define W2H_HALFS    (32 * W2H_STRIDE)   // 17664
#define COMBH_STRIDE 528                 // halfs; broadcast reads, no conflict concern
#define COMBH_HALFS  (8 * COMBH_STRIDE)  // 4224
#define TAIL_SMEM_BYTES ((W2H_HALFS + COMBH_HALFS) * 2 + 8 * 32 * 4 + 16)

__device__ float g_partial[(size_t)NTILE * 4 * 128 * 128];

__device__ __forceinline__ float crelu(float x) { return fminf(fmaxf(x, 0.f), 1.f); }
__device__ __forceinline__ uint32_t f2h2(float a, float b) {
    __half2 h = __floats2half2_rn(a, b);
    return *reinterpret_cast<uint32_t*>(&h);
}
__device__ __forceinline__ void mma16(float& c0, float& c1, float& c2, float& c3,
                                      uint32_t a0, uint32_t a1, uint32_t a2, uint32_t a3,
                                      uint32_t b0, uint32_t b1) {
    asm volatile(
        "mma.sync.aligned.m16n8k16.row.col.f32.f16.f16.f32 "
        "{%0,%1,%2,%3}, {%4,%5,%6,%7}, {%8,%9}, {%0,%1,%2,%3};"
        : "+f"(c0), "+f"(c1), "+f"(c2), "+f"(c3)
        : "r"(a0), "r"(a1), "r"(a2), "r"(a3), "r"(b0), "r"(b1));
}
__device__ __forceinline__ int owner_of(int s, int G) {
    return (int)((long)s * G / TOTS);
}

// ========== Kernel 1: FT GEMM, fp32-accum fp16 MMA, even stage-partition ==========
__global__ void __launch_bounds__(256, 1)
ft_kernel(const float* __restrict__ xp, const float* __restrict__ xo,
          const float* __restrict__ wp, const float* __restrict__ wo)
{
    extern __shared__ uint32_t sm[];
    const int tid = threadIdx.x, lane = tid & 31, wid = tid >> 5;
    const int G = gridDim.x, ib = blockIdx.x;
    int S = (int)((long)ib * TOTS / G);
    const int S_hi = (int)((long)(ib + 1) * TOTS / G);
    const uint32_t smb = (uint32_t)__cvta_generic_to_shared(sm);
    const int wm = (wid & 3) * 32;
    const int wn = (wid >> 2) * 64;

    while (S < S_hi) {
        const int t    = S / KSTPT;
        const int send = min(S_hi, (t + 1) * KSTPT);
        const int ks0  = S - t * KSTPT;
        const int len  = send - S;
        const int persp = t >> 5, mt = (t >> 1) & 15, nt = t & 1;
        const float* __restrict__ X = persp ? xo : xp;
        const float* __restrict__ W = persp ? wo : wp;
        const int m0 = mt * 128, n0 = nt * 128;
        const size_t kbase = (size_t)ks0 * KC;

        const float* aptr[8]; const float* bptr[8];
        uint32_t asw[8], bsw[8];
        #pragma unroll
        for (int j = 0; j < 8; j++) {
            int f = tid + j * 256, r = f >> 4, q = f & 15;
            aptr[j] = X + (size_t)(m0 + r) * INSZ + kbase + q * 4;
            bptr[j] = W + (size_t)(n0 + r) * INSZ + kbase + q * 4;
            asw[j] = smb + 4u * (r * ASTRW + q * 2);
            bsw[j] = smb + 4u * (A_WORDS + r * ASTRW + q * 2);
        }

        float acc[2][8][4];
        #pragma unroll
        for (int a = 0; a < 2; a++)
            #pragma unroll
            for (int b = 0; b < 8; b++)
                #pragma unroll
                for (int c = 0; c < 4; c++) acc[a][b][c] = 0.f;

        float4 ra[8], rb[8];
        #pragma unroll
        for (int j = 0; j < 8; j++) ra[j] = *reinterpret_cast<const float4*>(aptr[j]);
        #pragma unroll
        for (int j = 0; j < 8; j++) rb[j] = *reinterpret_cast<const float4*>(bptr[j]);
        #pragma unroll
        for (int j = 0; j < 8; j++) {
            uint32_t u0 = f2h2(ra[j].x, ra[j].y), u1 = f2h2(ra[j].z, ra[j].w);
            asm volatile("st.shared.v2.b32 [%0], {%1,%2};" :: "r"(asw[j]), "r"(u0), "r"(u1) : "memory");
            uint32_t v0 = f2h2(rb[j].x, rb[j].y), v1 = f2h2(rb[j].z, rb[j].w);
            asm volatile("st.shared.v2.b32 [%0], {%1,%2};" :: "r"(bsw[j]), "r"(v0), "r"(v1) : "memory");
        }
        __syncthreads();
        if (len > 1) {
            #pragma unroll
            for (int j = 0; j < 8; j++) ra[j] = *reinterpret_cast<const float4*>(aptr[j] + KC);
            #pragma unroll
            for (int j = 0; j < 8; j++) rb[j] = *reinterpret_cast<const float4*>(bptr[j] + KC);
        }

        for (int s2 = 0; s2 < len; s2++) {
            const int buf = s2 & 1;
            if (s2 + 1 < len) {
                const uint32_t boff = (uint32_t)((buf ^ 1) * BUF_WORDS * 4);
                #pragma unroll
                for (int j = 0; j < 8; j++) {
                    uint32_t u0 = f2h2(ra[j].x, ra[j].y), u1 = f2h2(ra[j].z, ra[j].w);
                    asm volatile("st.shared.v2.b32 [%0], {%1,%2};" :: "r"(asw[j] + boff), "r"(u0), "r"(u1) : "memory");
                    uint32_t v0 = f2h2(rb[j].x, rb[j].y), v1 = f2h2(rb[j].z, rb[j].w);
                    asm volatile("st.shared.v2.b32 [%0], {%1,%2};" :: "r"(bsw[j] + boff), "r"(v0), "r"(v1) : "memory");
                }
            }
            if (s2 + 2 < len) {
                const size_t ko = (size_t)(s2 + 2) * KC;
                #pragma unroll
                for (int j = 0; j < 8; j++) ra[j] = *reinterpret_cast<const float4*>(aptr[j] + ko);
                #pragma unroll
                for (int j = 0; j < 8; j++) rb[j] = *reinterpret_cast<const float4*>(bptr[j] + ko);
            }
            const uint32_t* sa = sm + buf * BUF_WORDS;
            const uint32_t* sb = sa + A_WORDS;
            #pragma unroll
            for (int kk = 0; kk < 4; kk++) {
                const int kw = kk * 8 + (lane & 3);
                uint32_t af[2][4], bf[8][2];
                #pragma unroll
                for (int mtl = 0; mtl < 2; mtl++) {
                    const int r = wm + mtl * 16 + (lane >> 2);
                    af[mtl][0] = sa[r * ASTRW + kw];
                    af[mtl][1] = sa[(r + 8) * ASTRW + kw];
                    af[mtl][2] = sa[r * ASTRW + kw + 4];
                    af[mtl][3] = sa[(r + 8) * ASTRW + kw + 4];
                }
                #pragma unroll
                for (int ntl = 0; ntl < 8; ntl++) {
                    const int rn = wn + ntl * 8 + (lane >> 2);
                    bf[ntl][0] = sb[rn * ASTRW + kw];
                    bf[ntl][1] = sb[rn * ASTRW + kw + 4];
                }
                #pragma unroll
                for (int mtl = 0; mtl < 2; mtl++)
                    #pragma unroll
                    for (int ntl = 0; ntl < 8; ntl++)
                        mma16(acc[mtl][ntl][0], acc[mtl][ntl][1],
                              acc[mtl][ntl][2], acc[mtl][ntl][3],
                              af[mtl][0], af[mtl][1], af[mtl][2], af[mtl][3],
                              bf[ntl][0], bf[ntl][1]);
            }
            __syncthreads();
        }

        const int slot = ib - owner_of(t * KSTPT, G);
        float* gp = g_partial + ((size_t)t * 4 + slot) * 16384;
        #pragma unroll
        for (int mtl = 0; mtl < 2; mtl++) {
            const int ml = wm + mtl * 16 + (lane >> 2);
            #pragma unroll
            for (int ntl = 0; ntl < 8; ntl++) {
                const int col = wn + ntl * 8 + (lane & 3) * 2;
                *reinterpret_cast<float2*>(&gp[(size_t)ml * 128 + col]) =
                    make_float2(acc[mtl][ntl][0], acc[mtl][ntl][1]);
                *reinterpret_cast<float2*>(&gp[(size_t)(ml + 8) * 128 + col]) =
                    make_float2(acc[mtl][ntl][2], acc[mtl][ntl][3]);
            }
        }
        S = send;
    }
}

// ========== Kernel 2: fused reduce + bias + crelu + tail MLP (fp16 smem staging) ====
__global__ void __launch_bounds__(256)
reduce_tail(const float* __restrict__ b1p, const float* __restrict__ b1o,
            const float* __restrict__ W2, const float* __restrict__ b2,
            const float* __restrict__ W3, const float* __restrict__ b3,
            const float* __restrict__ Wo, const float* __restrict__ bo,
            float* __restrict__ out, int G)
{
    extern __shared__ __half th[];
    __half* W2h   = th;                       // [32][552]
    __half* combh = th + W2H_HALFS;           // [8][528]
    float*  h1s   = reinterpret_cast<float*>(th + W2H_HALFS + COMBH_HALFS); // [8][32]
    const int tid = threadIdx.x, lane = tid & 31, wid = tid >> 5;
    const int R0 = blockIdx.x * 8;

    // phase 1: reduce splits + bias + crelu, store as fp16
    #pragma unroll
    for (int it = 0; it < 4; it++) {
        const int idx = it * 256 + tid;            // 8 rows x 128 f4
        const int row = idx >> 7, fq = idx & 127;
        const int m = R0 + row;
        const int f = fq * 4;
        const int persp = f >> 8, ntl = (f >> 7) & 1, c = f & 127;
        const int t = persp * 32 + (m >> 7) * 2 + ntl;
        const int o0 = (int)((long)t * KSTPT * G / TOTS);
        const int o1 = (int)(((long)t * KSTPT + KSTPT - 1) * G / TOTS);
        const int ns = o1 - o0 + 1;
        const float* gp = g_partial + (size_t)t * 4 * 16384 + (size_t)(m & 127) * 128 + c;
        float4 bv = (f < 256) ? *reinterpret_cast<const float4*>(&b1p[f])
                              : *reinterpret_cast<const float4*>(&b1o[f - 256]);
        float4 s = bv;
        for (int sl = 0; sl < ns; sl++) {
            float4 v = *reinterpret_cast<const float4*>(gp + (size_t)sl * 16384);
            s.x += v.x; s.y += v.y; s.z += v.z; s.w += v.w;
        }
        __half2 h0 = __floats2half2_rn(crelu(s.x), crelu(s.y));
        __half2 h1v = __floats2half2_rn(crelu(s.z), crelu(s.w));
        *reinterpret_cast<uint2*>(&combh[row * COMBH_STRIDE + f]) =
            make_uint2(*reinterpret_cast<uint32_t*>(&h0), *reinterpret_cast<uint32_t*>(&h1v));
    }
    // stage W2 as fp16
    #pragma unroll
    for (int it = 0; it < 16; it++) {
        const int idx = it * 256 + tid;            // 4096 f4 = 32x512 floats
        const int j = idx >> 7, k = (idx & 127) * 4;
        float4 w = *reinterpret_cast<const float4*>(&W2[j * 512 + k]);
        __half2 h0 = __floats2half2_rn(w.x, w.y);
        __half2 h1v = __floats2half2_rn(w.z, w.w);
        *reinterpret_cast<uint2*>(&W2h[j * W2H_STRIDE + k]) =
            make_uint2(*reinterpret_cast<uint32_t*>(&h0), *reinterpret_cast<uint32_t*>(&h1v));
    }
    __syncthreads();

    // phase 2: warp = row, lane = output j; hfma2 with fp32 promotion every 32 elems
    {
        const int row = wid;
        const uint4* w4 = reinterpret_cast<const uint4*>(&W2h[lane * W2H_STRIDE]);
        const uint4* c4 = reinterpret_cast<const uint4*>(&combh[row * COMBH_STRIDE]);
        float a = b2[lane];
        #pragma unroll 4
        for (int kb = 0; kb < 16; kb++) {          // 16 blocks of 32 halfs (4 uint4)
            __half2 s0 = __float2half2_rn(0.f), s1 = __float2half2_rn(0.f);
            #pragma unroll
            for (int i = 0; i < 4; i++) {
                uint4 wv = w4[kb * 4 + i];
                uint4 cv = c4[kb * 4 + i];
                s0 = __hfma2(*reinterpret_cast<__half2*>(&wv.x),
                             *reinterpret_cast<__half2*>(&cv.x), s0);
                s1 = __hfma2(*reinterpret_cast<__half2*>(&wv.y),
                             *reinterpret_cast<__half2*>(&cv.y), s1);
                s0 = __hfma2(*reinterpret_cast<__half2*>(&wv.z),
                             *reinterpret_cast<__half2*>(&cv.z), s0);
                s1 = __hfma2(*reinterpret_cast<__half2*>(&wv.w),
                             *reinterpret_cast<__half2*>(&cv.w), s1);
            }
            float2 f0 = __half22float2(s0);
            float2 f1 = __half22float2(s1);
            a += (f0.x + f0.y) + (f1.x + f1.y);
        }
        h1s[row * 32 + lane] = crelu(a);
        __syncwarp();
        float h2a = b3[lane], h2b = 0.f;
        #pragma unroll
        for (int k = 0; k < 32; k += 2) {
            h2a += W3[lane * 32 + k] * h1s[row * 32 + k];
            h2b += W3[lane * 32 + k + 1] * h1s[row * 32 + k + 1];
        }
        float h2 = crelu(h2a + h2b);
        float v = h2 * Wo[lane];
        #pragma unroll
        for (int o = 16; o; o >>= 1) v += __shfl_xor_sync(0xFFFFFFFFu, v, o);
        if (lane == 0) out[R0 + row] = crelu(v + bo[0]);
    }
}

extern "C" void kernel_launch(void* const* d_in, const int* in_sizes, int n_in,
                              void* d_out, int out_size)
{
    const float* xp  = (const float*)d_in[0];
    const float* xo  = (const float*)d_in[1];
    const float* W1p = (const float*)d_in[2];
    const float* b1p = (const float*)d_in[3];
    const float* W1o = (const float*)d_in[4];
    const float* b1o = (const float*)d_in[5];
    const float* W2  = (const float*)d_in[6];
    const float* b2  = (const float*)d_in[7];
    const float* W3  = (const float*)d_in[8];
    const float* b3  = (const float*)d_in[9];
    const float* Wo  = (const float*)d_in[10];
    const float* bo  = (const float*)d_in[11];

    static int grid_ft = 0;
    if (grid_ft == 0) {
        int smc = 148;
        cudaDeviceGetAttribute(&smc, cudaDevAttrMultiProcessorCount, 0);
        if (smc > 160) smc = 160;
        if (smc < 64)  smc = 64;
        grid_ft = smc;
        cudaFuncSetAttribute(ft_kernel, cudaFuncAttributeMaxDynamicSharedMemorySize,
                             SMEM_BYTES);
        cudaFuncSetAttribute(reduce_tail, cudaFuncAttributeMaxDynamicSharedMemorySize,
                             TAIL_SMEM_BYTES);
    }
    ft_kernel<<<grid_ft, 256, SMEM_BYTES>>>(xp, xo, W1p, W1o);
    reduce_tail<<<256, 256, TAIL_SMEM_BYTES>>>(b1p, b1o, W2, b2, W3, b3, Wo, bo,
                                               (float*)d_out, grid_ft);
}